// round 4
// baseline (speedup 1.0000x reference)
#include <cuda_runtime.h>
#include <cstdint>
#include <cstddef>

// Problem constants
#define B_   32
#define D_   512
#define P_   1024          // 32*32 spatial positions per batch image
#define N_   32768         // B_*P_
#define K_   4096
#define TM   128           // rows (n) per block
#define TK   128           // codes (k) per block k-tile
#define DB   32            // d-chunk staged in smem
#define NCH  (D_/DB)       // 16 chunks
#define NKT  (K_/TK)       // 32 k-tiles
#define NBLK (N_/TM)       // 256 blocks
#define BST  132           // Bs row stride (floats), padded

__device__ float g_enorm[K_];
__device__ float g_losspart[NBLK];

// ---------------------------------------------------------------------------
// enorm[k] = sum_d E[k][d]^2   (fp32 on original values, matches reference d3)
// ---------------------------------------------------------------------------
__global__ void enorm_kernel(const float* __restrict__ E) {
    int k    = blockIdx.x * 8 + (threadIdx.x >> 5);
    int lane = threadIdx.x & 31;
    const float* row = E + (size_t)k * D_;
    float s = 0.f;
#pragma unroll
    for (int d = lane; d < D_; d += 32) {
        float v = row[d];
        s = fmaf(v, v, s);
    }
#pragma unroll
    for (int o = 16; o; o >>= 1) s += __shfl_xor_sync(0xffffffffu, s, o);
    if (lane == 0) g_enorm[k] = s;
}

// ---------------------------------------------------------------------------
// Main fused kernel: fp32 GEMM (z @ E^T) + running argmin + gather +
// transpose + loss partials. One block = 128 consecutive n (one batch image).
// z[n,d] = x[b*D_*P_ + d*P_ + p],  n = b*P_ + p
// Thread tile: 8 rows x 8 cols (split 4+4 at stride 64 to keep LDS.128
// conflict-free). 256 threads, 2 CTAs/SM, 256 blocks = exactly 1 wave.
// ---------------------------------------------------------------------------
__global__ __launch_bounds__(256, 2)
void vq_main(const float* __restrict__ x, const float* __restrict__ E,
             float* __restrict__ out)
{
    // 4096 (As: [32][128]) + 4224 (Bs: [32][132]) floats = 33280 bytes.
    // Post-GEMM the same memory is reused for the argmin/loss reductions.
    __shared__ float s_mem[DB * TM + DB * BST];
    float* As = s_mem;            // [DB][TM]
    float* Bs = s_mem + DB * TM;  // [DB][BST]

    const int tid = threadIdx.x;
    const int tx  = tid & 15;          // col group: cols tx*4..+3 and +64
    const int ty  = tid >> 4;          // row group: rows ty*4..+3 and +64
    const int n0  = blockIdx.x * TM;
    const int b   = n0 >> 10;
    const int p0  = n0 & (P_ - 1);
    const float* xb = x + (size_t)b * (D_ * P_) + p0;   // xb[d*P_ + p]

    float bestv[8];
    int   besti[8];
#pragma unroll
    for (int i = 0; i < 8; i++) { bestv[i] = 3.402823e38f; besti[i] = 0; }

    // staging decomposition
    const int a_dofs = tid >> 7;       // 0..1
    const int a_p    = tid & 127;
    const int b_d4   = tid >> 5;       // warp-uniform: float4 index in 32-d chunk
    const int b_k    = tid & 31;       // lane -> k within group of 32

    for (int kt = 0; kt < NKT; ++kt) {
        const int k0 = kt * TK;
        float acc[8][8];
#pragma unroll
        for (int i = 0; i < 8; i++)
#pragma unroll
            for (int j = 0; j < 8; j++) acc[i][j] = 0.f;

        float  rA[16];
        float4 rB[4];

        // prologue: load chunk 0 into registers
#pragma unroll
        for (int i = 0; i < 16; i++)
            rA[i] = xb[(size_t)(a_dofs + 2 * i) * P_ + a_p];
#pragma unroll
        for (int i = 0; i < 4; i++)
            rB[i] = *reinterpret_cast<const float4*>(
                E + (size_t)(k0 + b_k + 32 * i) * D_ + b_d4 * 4);

        for (int dc = 0; dc < NCH; ++dc) {
            __syncthreads();  // previous chunk's compute done
#pragma unroll
            for (int i = 0; i < 16; i++)
                As[(a_dofs + 2 * i) * TM + a_p] = rA[i];
#pragma unroll
            for (int i = 0; i < 4; i++) {
                Bs[(b_d4 * 4 + 0) * BST + b_k + 32 * i] = rB[i].x;
                Bs[(b_d4 * 4 + 1) * BST + b_k + 32 * i] = rB[i].y;
                Bs[(b_d4 * 4 + 2) * BST + b_k + 32 * i] = rB[i].z;
                Bs[(b_d4 * 4 + 3) * BST + b_k + 32 * i] = rB[i].w;
            }
            __syncthreads();

            // prefetch next chunk (hidden under compute)
            if (dc + 1 < NCH) {
                const int dnext = (dc + 1) * DB;
#pragma unroll
                for (int i = 0; i < 16; i++)
                    rA[i] = xb[(size_t)(dnext + a_dofs + 2 * i) * P_ + a_p];
#pragma unroll
                for (int i = 0; i < 4; i++)
                    rB[i] = *reinterpret_cast<const float4*>(
                        E + (size_t)(k0 + b_k + 32 * i) * D_ + dnext + b_d4 * 4);
            }

            // compute on current smem chunk
#pragma unroll
            for (int dd = 0; dd < DB; ++dd) {
                const float* Ar = As + dd * TM;
                const float* Br = Bs + dd * BST;
                float4 a0 = *reinterpret_cast<const float4*>(Ar + ty * 4);
                float4 a1 = *reinterpret_cast<const float4*>(Ar + ty * 4 + 64);
                float4 b0 = *reinterpret_cast<const float4*>(Br + tx * 4);
                float4 b1 = *reinterpret_cast<const float4*>(Br + tx * 4 + 64);
                float a[8]  = {a0.x, a0.y, a0.z, a0.w, a1.x, a1.y, a1.z, a1.w};
                float bb[8] = {b0.x, b0.y, b0.z, b0.w, b1.x, b1.y, b1.z, b1.w};
#pragma unroll
                for (int i = 0; i < 8; i++)
#pragma unroll
                    for (int j = 0; j < 8; j++)
                        acc[i][j] = fmaf(a[i], bb[j], acc[i][j]);
            }
        }

        // epilogue: s = ||e_k||^2 - 2 * (z . e_k), running min (first-k ties)
#pragma unroll
        for (int j = 0; j < 8; j++) {
            const int k = k0 + tx * 4 + (j & 3) + ((j >> 2) << 6);
            const float en = g_enorm[k];
#pragma unroll
            for (int i = 0; i < 8; i++) {
                float s = fmaf(-2.f, acc[i][j], en);
                if (s < bestv[i]) { bestv[i] = s; besti[i] = k; }
            }
        }
    }

    // -------- cross-thread argmin reduction (16 threads per row) --------
    __syncthreads();
    float* redv  = s_mem;                                // [16][TM]
    int*   redi  = reinterpret_cast<int*>(s_mem + 16 * TM);
    int*   kbest = reinterpret_cast<int*>(s_mem + 32 * TM);
    float* lred  = s_mem + 33 * TM;                      // 256 floats

#pragma unroll
    for (int i = 0; i < 8; i++) {
        const int r = ty * 4 + (i & 3) + ((i >> 2) << 6);
        redv[tx * TM + r] = bestv[i];
        redi[tx * TM + r] = besti[i];
    }
    __syncthreads();
    if (tid < TM) {
        float bv = redv[tid];
        int   bi = redi[tid];
#pragma unroll
        for (int t = 1; t < 16; t++) {
            float v  = redv[t * TM + tid];
            int   ii = redi[t * TM + tid];
            if (v < bv || (v == bv && ii < bi)) { bv = v; bi = ii; }
        }
        kbest[tid] = bi;
    }
    __syncthreads();

    // -------- gather + transpose write + loss (elementwise fp32) --------
    const int p      = tid & 127;
    const int dstart = tid >> 7;
    const int myk    = kbest[p];
    const float* Er  = E + (size_t)myk * D_;
    float* ob        = out + (size_t)b * (D_ * P_) + p0;
    float lsum = 0.f;
#pragma unroll 4
    for (int d = dstart; d < D_; d += 2) {
        float q = Er[d];
        float z = xb[(size_t)d * P_ + p];
        ob[(size_t)d * P_ + p] = q;
        float df = z - q;
        lsum = fmaf(df, df, lsum);
    }

    __syncthreads();
    lred[tid] = lsum;
    __syncthreads();
    for (int s = 128; s > 0; s >>= 1) {
        if (tid < s) lred[tid] += lred[tid + s];
        __syncthreads();
    }
    if (tid == 0) g_losspart[blockIdx.x] = lred[0];
}

// ---------------------------------------------------------------------------
// Final loss: loss = e_loss + 0.25*e_loss, e_loss = mean((z-q)^2)
// ---------------------------------------------------------------------------
__global__ void loss_kernel(float* __restrict__ out, int write_loss) {
    __shared__ float sh[NBLK];
    int tid = threadIdx.x;
    sh[tid] = g_losspart[tid];
    __syncthreads();
    for (int s = NBLK / 2; s > 0; s >>= 1) {
        if (tid < s) sh[tid] += sh[tid + s];
        __syncthreads();
    }
    if (tid == 0 && write_loss) {
        float m = sh[0] / (float)(N_ * D_);
        out[(size_t)N_ * D_] = m + 0.25f * m;
    }
}

extern "C" void kernel_launch(void* const* d_in, const int* in_sizes, int n_in,
                              void* d_out, int out_size) {
    const float* x = (const float*)d_in[0];
    const float* E = (const float*)d_in[1];
    if (n_in >= 2 && in_sizes[0] == K_ * D_ && in_sizes[1] == N_ * D_) {
        const float* t = x; x = E; E = t;   // defensive input-order swap
    }
    float* out = (float*)d_out;

    enorm_kernel<<<K_ / 8, 256>>>(E);
    vq_main<<<NBLK, 256>>>(x, E, out);
    loss_kernel<<<1, NBLK>>>(out, out_size > N_ * D_ ? 1 : 0);
}

// round 6
// speedup vs baseline: 1.1134x; 1.1134x over previous
#include <cuda_runtime.h>
#include <cstdint>
#include <cstddef>

// Problem constants
#define B_   32
#define D_   512
#define P_   1024          // 32*32 spatial positions per batch image
#define N_   32768         // B_*P_
#define K_   4096
#define TM   128           // rows (n) per block
#define TK   128           // codes (k) per block k-tile
#define DB   32            // d-chunk staged in smem
#define NCH  (D_/DB)       // 16 chunks
#define NKT  (K_/TK)       // 32 k-tiles
#define NBLK (N_/TM)       // 256 blocks
#define BST  132           // Bs row stride (floats), padded

typedef unsigned long long u64;

__device__ float g_enorm[K_];
__device__ float g_losspart[NBLK];

// ---- packed f32x2 helpers (sm_100+ PTX; SASS FFMA2 = 2x scalar FFMA tput) ----
__device__ __forceinline__ u64 pack_dup(float v) {
    u64 r; asm("mov.b64 %0, {%1, %1};" : "=l"(r) : "f"(v)); return r;
}
__device__ __forceinline__ u64 pack2(float lo, float hi) {
    u64 r; asm("mov.b64 %0, {%1, %2};" : "=l"(r) : "f"(lo), "f"(hi)); return r;
}
__device__ __forceinline__ void fma2(u64& d, u64 a, u64 b) {
    asm("fma.rn.f32x2 %0, %1, %2, %0;" : "+l"(d) : "l"(a), "l"(b));
}
__device__ __forceinline__ void unpack2(float& lo, float& hi, u64 v) {
    asm("mov.b64 {%0, %1}, %2;" : "=f"(lo), "=f"(hi) : "l"(v));
}

// ---------------------------------------------------------------------------
// enorm[k] = sum_d E[k][d]^2   (fp32 on original values, matches reference d3)
// ---------------------------------------------------------------------------
__global__ void enorm_kernel(const float* __restrict__ E) {
    int k    = blockIdx.x * 8 + (threadIdx.x >> 5);
    int lane = threadIdx.x & 31;
    const float* row = E + (size_t)k * D_;
    float s = 0.f;
#pragma unroll
    for (int d = lane; d < D_; d += 32) {
        float v = row[d];
        s = fmaf(v, v, s);
    }
#pragma unroll
    for (int o = 16; o; o >>= 1) s += __shfl_xor_sync(0xffffffffu, s, o);
    if (lane == 0) g_enorm[k] = s;
}

// ---------------------------------------------------------------------------
// Main fused kernel: fp32 GEMM (z @ E^T) via packed FFMA2 + running argmin +
// gather + transpose + loss partials. One block = 128 consecutive n.
// z[n,d] = x[b*D_*P_ + d*P_ + p],  n = b*P_ + p
// Thread tile: 8 rows x 8 cols; cols held as 4 f32x2 pairs.
// Row/col fragments split 4+4 at stride 64 for conflict-free LDS.128.
// 256 threads, 2 CTAs/SM, 256 blocks = exactly 1 wave.
// ---------------------------------------------------------------------------
__global__ __launch_bounds__(256, 2)
void vq_main(const float* __restrict__ x, const float* __restrict__ E,
             float* __restrict__ out)
{
    // 4096 (As: [32][128]) + 4224 (Bs: [32][132]) floats = 33280 bytes.
    // Post-GEMM the same memory is reused for the argmin/loss reductions.
    __shared__ float s_mem[DB * TM + DB * BST];
    float* As = s_mem;            // [DB][TM]
    float* Bs = s_mem + DB * TM;  // [DB][BST]

    const int tid = threadIdx.x;
    const int tx  = tid & 15;          // col group: cols tx*4..+3 and +64
    const int ty  = tid >> 4;          // row group: rows ty*4..+3 and +64
    const int n0  = blockIdx.x * TM;
    const int b   = n0 >> 10;
    const int p0  = n0 & (P_ - 1);
    const float* xb = x + (size_t)b * (D_ * P_) + p0;   // xb[d*P_ + p]

    float bestv[8];
    int   besti[8];
#pragma unroll
    for (int i = 0; i < 8; i++) { bestv[i] = 3.402823e38f; besti[i] = 0; }

    // staging decomposition
    const int a_dofs = tid >> 7;       // 0..1
    const int a_p    = tid & 127;
    const int b_d4   = tid >> 5;       // warp-uniform: float4 index in 32-d chunk
    const int b_k    = tid & 31;       // lane -> k within group of 32

    for (int kt = 0; kt < NKT; ++kt) {
        const int k0 = kt * TK;
        // acc[i][j]: rows i (ty*4 + (i&3) + (i>>2)*64),
        // col pairs j: cols tx*4 + 2*(j&1) + (j>>1)*64, +1
        u64 acc[8][4];
#pragma unroll
        for (int i = 0; i < 8; i++)
#pragma unroll
            for (int j = 0; j < 4; j++) acc[i][j] = 0ull;

        float  rA[16];
        float4 rB[4];

        // prologue: load chunk 0 into registers
#pragma unroll
        for (int i = 0; i < 16; i++)
            rA[i] = xb[(size_t)(a_dofs + 2 * i) * P_ + a_p];
#pragma unroll
        for (int i = 0; i < 4; i++)
            rB[i] = *reinterpret_cast<const float4*>(
                E + (size_t)(k0 + b_k + 32 * i) * D_ + b_d4 * 4);

        for (int dc = 0; dc < NCH; ++dc) {
            __syncthreads();  // previous chunk's compute done
#pragma unroll
            for (int i = 0; i < 16; i++)
                As[(a_dofs + 2 * i) * TM + a_p] = rA[i];
#pragma unroll
            for (int i = 0; i < 4; i++) {
                Bs[(b_d4 * 4 + 0) * BST + b_k + 32 * i] = rB[i].x;
                Bs[(b_d4 * 4 + 1) * BST + b_k + 32 * i] = rB[i].y;
                Bs[(b_d4 * 4 + 2) * BST + b_k + 32 * i] = rB[i].z;
                Bs[(b_d4 * 4 + 3) * BST + b_k + 32 * i] = rB[i].w;
            }
            __syncthreads();

            // prefetch next chunk (hidden under compute)
            if (dc + 1 < NCH) {
                const int dnext = (dc + 1) * DB;
#pragma unroll
                for (int i = 0; i < 16; i++)
                    rA[i] = xb[(size_t)(dnext + a_dofs + 2 * i) * P_ + a_p];
#pragma unroll
                for (int i = 0; i < 4; i++)
                    rB[i] = *reinterpret_cast<const float4*>(
                        E + (size_t)(k0 + b_k + 32 * i) * D_ + dnext + b_d4 * 4);
            }

            // compute on current smem chunk (packed FFMA2)
#pragma unroll
            for (int dd = 0; dd < DB; ++dd) {
                const float* Ar = As + dd * TM;
                const float* Br = Bs + dd * BST;
                float4 a0 = *reinterpret_cast<const float4*>(Ar + ty * 4);
                float4 a1 = *reinterpret_cast<const float4*>(Ar + ty * 4 + 64);
                float4 b0 = *reinterpret_cast<const float4*>(Br + tx * 4);
                float4 b1 = *reinterpret_cast<const float4*>(Br + tx * 4 + 64);
                const float a[8] = {a0.x, a0.y, a0.z, a0.w,
                                    a1.x, a1.y, a1.z, a1.w};
                u64 bp[4];
                bp[0] = pack2(b0.x, b0.y);
                bp[1] = pack2(b0.z, b0.w);
                bp[2] = pack2(b1.x, b1.y);
                bp[3] = pack2(b1.z, b1.w);
#pragma unroll
                for (int i = 0; i < 8; i++) {
                    u64 ap = pack_dup(a[i]);
#pragma unroll
                    for (int j = 0; j < 4; j++)
                        fma2(acc[i][j], ap, bp[j]);
                }
            }
        }

        // epilogue: s = ||e_k||^2 - 2 * (z . e_k), running min (first-k ties)
#pragma unroll
        for (int j = 0; j < 4; j++) {
            const int kb = k0 + tx * 4 + ((j & 1) << 1) + ((j >> 1) << 6);
            const float en0 = g_enorm[kb];
            const float en1 = g_enorm[kb + 1];
#pragma unroll
            for (int i = 0; i < 8; i++) {
                float lo, hi;
                unpack2(lo, hi, acc[i][j]);
                float s0 = fmaf(-2.f, lo, en0);
                float s1 = fmaf(-2.f, hi, en1);
                if (s0 < bestv[i]) { bestv[i] = s0; besti[i] = kb; }
                if (s1 < bestv[i]) { bestv[i] = s1; besti[i] = kb + 1; }
            }
        }
    }

    // -------- cross-thread argmin reduction (16 threads per row) --------
    __syncthreads();
    float* redv  = s_mem;                                // [16][TM]
    int*   redi  = reinterpret_cast<int*>(s_mem + 16 * TM);
    int*   kbest = reinterpret_cast<int*>(s_mem + 32 * TM);
    float* lred  = s_mem + 33 * TM;                      // 256 floats

#pragma unroll
    for (int i = 0; i < 8; i++) {
        const int r = ty * 4 + (i & 3) + ((i >> 2) << 6);
        redv[tx * TM + r] = bestv[i];
        redi[tx * TM + r] = besti[i];
    }
    __syncthreads();
    if (tid < TM) {
        float bv = redv[tid];
        int   bi = redi[tid];
#pragma unroll
        for (int t = 1; t < 16; t++) {
            float v  = redv[t * TM + tid];
            int   ii = redi[t * TM + tid];
            if (v < bv || (v == bv && ii < bi)) { bv = v; bi = ii; }
        }
        kbest[tid] = bi;
    }
    __syncthreads();

    // -------- gather + transpose write + loss (elementwise fp32) --------
    const int p      = tid & 127;
    const int dstart = tid >> 7;
    const int myk    = kbest[p];
    const float* Er  = E + (size_t)myk * D_;
    float* ob        = out + (size_t)b * (D_ * P_) + p0;
    float lsum = 0.f;
#pragma unroll 4
    for (int d = dstart; d < D_; d += 2) {
        float q = Er[d];
        float z = xb[(size_t)d * P_ + p];
        ob[(size_t)d * P_ + p] = q;
        float df = z - q;
        lsum = fmaf(df, df, lsum);
    }

    __syncthreads();
    lred[tid] = lsum;
    __syncthreads();
    for (int s = 128; s > 0; s >>= 1) {
        if (tid < s) lred[tid] += lred[tid + s];
        __syncthreads();
    }
    if (tid == 0) g_losspart[blockIdx.x] = lred[0];
}

// ---------------------------------------------------------------------------
// Final loss: loss = e_loss + 0.25*e_loss, e_loss = mean((z-q)^2)
// ---------------------------------------------------------------------------
__global__ void loss_kernel(float* __restrict__ out, int write_loss) {
    __shared__ float sh[NBLK];
    int tid = threadIdx.x;
    sh[tid] = g_losspart[tid];
    __syncthreads();
    for (int s = NBLK / 2; s > 0; s >>= 1) {
        if (tid < s) sh[tid] += sh[tid + s];
        __syncthreads();
    }
    if (tid == 0 && write_loss) {
        float m = sh[0] / (float)(N_ * D_);
        out[(size_t)N_ * D_] = m + 0.25f * m;
    }
}

extern "C" void kernel_launch(void* const* d_in, const int* in_sizes, int n_in,
                              void* d_out, int out_size) {
    const float* x = (const float*)d_in[0];
    const float* E = (const float*)d_in[1];
    if (n_in >= 2 && in_sizes[0] == K_ * D_ && in_sizes[1] == N_ * D_) {
        const float* t = x; x = E; E = t;   // defensive input-order swap
    }
    float* out = (float*)d_out;

    enorm_kernel<<<K_ / 8, 256>>>(E);
    vq_main<<<NBLK, 256>>>(x, E, out);
    loss_kernel<<<1, NBLK>>>(out, out_size > N_ * D_ ? 1 : 0);
}

// round 9
// speedup vs baseline: 3.6629x; 3.2899x over previous
#include <cuda_runtime.h>
#include <cuda_bf16.h>
#include <cstdint>
#include <cstddef>

// Problem constants
#define B_   32
#define D_   512
#define P_   1024
#define N_   32768
#define K_   4096
#define TM   128           // rows per CTA
#define TK   32            // codes per k-tile
#define NKT  (K_/TK)       // 128 k-tiles
#define NBLK (N_/TM)       // 256 blocks
#define EPS  2.0f          // bf16 score error window (~7 sigma)

#define ASTRIDE 1040       // bytes per staged row (520 bf16): conflict-free ldmatrix

// Dynamic smem layout (bytes)
#define SM_EN    0                       // float[4096] exact ||e_k||^2
#define SM_KB    16384                   // int[128]
#define SM_LRED  16896                   // float[256]
#define SM_A     18432                   // 128 rows * 1040 B = 133120
#define SM_B0    151552                  // 2 buffers * 33280 B
#define SM_BSZ   (TK * ASTRIDE)          // 33280
#define SM_TOTAL 218112

__device__ float g_enorm[K_];
__device__ float g_losspart[NBLK];
__device__ __nv_bfloat16 g_Ebf[(size_t)K_ * D_];   // E bf16 row-major [k][d]
__device__ __nv_bfloat16 g_Zbf[(size_t)N_ * D_];   // z bf16 row-major [n][d]

// ---------------- PTX helpers (baseline ISA only — no sm_103a features) ----
__device__ __forceinline__ uint32_t smem_u32(const void* p) {
    uint32_t a;
    asm("{ .reg .u64 t; cvta.to.shared.u64 t, %1; cvt.u32.u64 %0, t; }"
        : "=r"(a) : "l"(p));
    return a;
}
__device__ __forceinline__ void cp_async16(uint32_t dst, const void* src) {
    asm volatile("cp.async.cg.shared.global [%0], [%1], 16;"
                 :: "r"(dst), "l"(src) : "memory");
}
__device__ __forceinline__ void cp_commit() {
    asm volatile("cp.async.commit_group;" ::: "memory");
}
__device__ __forceinline__ void cp_wait0() {
    asm volatile("cp.async.wait_group 0;" ::: "memory");
}
__device__ __forceinline__ void ldsm_x4(uint32_t* r, uint32_t addr) {
    asm volatile("ldmatrix.sync.aligned.m8n8.x4.shared.b16 {%0,%1,%2,%3}, [%4];"
                 : "=r"(r[0]), "=r"(r[1]), "=r"(r[2]), "=r"(r[3]) : "r"(addr));
}
__device__ __forceinline__ void mma16816(float* c, const uint32_t* a,
                                         uint32_t b0, uint32_t b1) {
    asm volatile(
        "mma.sync.aligned.m16n8k16.row.col.f32.bf16.bf16.f32 "
        "{%0,%1,%2,%3}, {%4,%5,%6,%7}, {%8,%9}, {%0,%1,%2,%3};"
        : "+f"(c[0]), "+f"(c[1]), "+f"(c[2]), "+f"(c[3])
        : "r"(a[0]), "r"(a[1]), "r"(a[2]), "r"(a[3]), "r"(b0), "r"(b1));
}

// ---------------------------------------------------------------------------
// Pre-pass: E fp32 -> bf16 row-major
// ---------------------------------------------------------------------------
__global__ void convE_kernel(const float* __restrict__ E) {
    int i = blockIdx.x * blockDim.x + threadIdx.x;          // float2 pairs
    const float2 v = reinterpret_cast<const float2*>(E)[i];
    __nv_bfloat162 b;
    b.x = __float2bfloat16_rn(v.x);
    b.y = __float2bfloat16_rn(v.y);
    reinterpret_cast<__nv_bfloat162*>(g_Ebf)[i] = b;
}

// ---------------------------------------------------------------------------
// Pre-pass: transpose-convert x[b][d][p] -> g_Zbf[n][d] bf16  (n = b*1024+p)
// grid 4096 = 32 b * 16 dchunk * 8 pchunk, 256 threads
// ---------------------------------------------------------------------------
__global__ void convZ_kernel(const float* __restrict__ x) {
    __shared__ float t[32][129];
    const int bz = blockIdx.x;
    const int b  = bz >> 7;
    const int r  = bz & 127;
    const int dc = r >> 3;
    const int pc = r & 7;
    const int tid = threadIdx.x;

    const float* xb = x + (size_t)b * (D_ * P_) + (size_t)(dc * 32) * P_ + pc * 128;
#pragma unroll
    for (int j = 0; j < 16; j++) {
        int e = tid + j * 256;
        int d = e >> 7, p = e & 127;
        t[d][p] = xb[(size_t)d * P_ + p];
    }
    __syncthreads();

    const int n0 = b * P_ + pc * 128;
#pragma unroll
    for (int j = 0; j < 8; j++) {
        int f = tid + j * 256;               // 2048 u32 outputs
        int nl = f >> 4, d2 = f & 15;
        __nv_bfloat162 v;
        v.x = __float2bfloat16_rn(t[d2 * 2][nl]);
        v.y = __float2bfloat16_rn(t[d2 * 2 + 1][nl]);
        reinterpret_cast<__nv_bfloat162*>(g_Zbf)[(size_t)(n0 + nl) * (D_ / 2) + dc * 16 + d2] = v;
    }
}

// ---------------------------------------------------------------------------
// enorm[k] = sum_d E[k][d]^2  (exact fp32 on originals)
// ---------------------------------------------------------------------------
__global__ void enorm_kernel(const float* __restrict__ E) {
    int k    = blockIdx.x * 8 + (threadIdx.x >> 5);
    int lane = threadIdx.x & 31;
    const float* row = E + (size_t)k * D_;
    float s = 0.f;
#pragma unroll
    for (int d = lane; d < D_; d += 32) {
        float v = row[d];
        s = fmaf(v, v, s);
    }
#pragma unroll
    for (int o = 16; o; o >>= 1) s += __shfl_xor_sync(0xffffffffu, s, o);
    if (lane == 0) g_enorm[k] = s;
}

// ---------------------------------------------------------------------------
// Main: bf16 mma.sync GEMM + eps-window argmin + exact refinement + gather +
// transpose + loss. CTA = 128 rows, 8 warps (16 rows each), 256 threads.
// ---------------------------------------------------------------------------
__global__ __launch_bounds__(256, 1)
void vq_main(const float* __restrict__ x, const float* __restrict__ E,
             float* __restrict__ out)
{
    extern __shared__ unsigned char sm_raw[];
    const uint32_t smem_base = smem_u32(sm_raw);
    float* en_sm = reinterpret_cast<float*>(sm_raw + SM_EN);
    int*   kbest = reinterpret_cast<int*>(sm_raw + SM_KB);
    float* lred  = reinterpret_cast<float*>(sm_raw + SM_LRED);

    const int tid  = threadIdx.x;
    const int wid  = tid >> 5;
    const int lane = tid & 31;
    const int n0   = blockIdx.x * TM;
    const int b    = n0 >> 10;
    const int p0   = n0 & (P_ - 1);
    const float* xb = x + (size_t)b * (D_ * P_) + p0;   // xb[d*P_ + p]

    // exact enorm -> smem
#pragma unroll
    for (int j = 0; j < 16; j++) en_sm[tid + j * 256] = g_enorm[tid + j * 256];

    // Stage A: 128 rows x 64 16B-chunks (row stride 1040 B)
#pragma unroll
    for (int i = 0; i < 32; i++) {
        int c = tid + i * 256;               // 0..8191
        int m = c >> 6, d8 = c & 63;
        cp_async16(smem_base + SM_A + (uint32_t)(m * ASTRIDE + d8 * 16),
                   g_Zbf + ((size_t)(n0 + m) * D_ + d8 * 8));
    }
    // Stage B tile 0: 32 rows x 64 chunks
#pragma unroll
    for (int i = 0; i < 8; i++) {
        int c = tid + i * 256;               // 0..2047
        int kk = c >> 6, d8 = c & 63;
        cp_async16(smem_base + SM_B0 + (uint32_t)(kk * ASTRIDE + d8 * 16),
                   g_Ebf + ((size_t)kk * D_ + d8 * 8));
    }
    cp_commit();
    cp_wait0();
    __syncthreads();

    // ldmatrix base addresses
    const uint32_t aAddr = smem_base + SM_A
        + (uint32_t)((wid * 16 + (lane & 15)) * ASTRIDE + ((lane >> 4) * 8) * 2);
    const int bj   = lane >> 3;              // 0..3
    const int brow = ((bj >> 1) * 8) + (lane & 7);
    const int bkof = (bj & 1) * 16;          // bytes: (j&1)*8 bf16

    // per-thread trackers: slot 0 -> row g, slot 1 -> row g+8 (g = lane>>2)
    float bestv[2] = {3.402823e38f, 3.402823e38f};
    int   besti[2] = {0, 0};
    float cv[2][4];
    int   ci[2][4];
#pragma unroll
    for (int s2 = 0; s2 < 2; s2++)
#pragma unroll
        for (int j = 0; j < 4; j++) { cv[s2][j] = 3.402823e38f; ci[s2][j] = 0; }

    const int tig = lane & 3;                // col pair within n-tile

    for (int t = 0; t < NKT; ++t) {
        const int cur = t & 1;

        // prefetch next B tile (overlaps compute)
        if (t + 1 < NKT) {
            const int k0n = (t + 1) * TK;
#pragma unroll
            for (int i = 0; i < 8; i++) {
                int c = tid + i * 256;
                int kk = c >> 6, d8 = c & 63;
                cp_async16(smem_base + SM_B0 + (uint32_t)((cur ^ 1) * SM_BSZ
                                                          + kk * ASTRIDE + d8 * 16),
                           g_Ebf + ((size_t)(k0n + kk) * D_ + d8 * 8));
            }
        }
        cp_commit();

        // GEMM on current tile: 4 n-tiles x 32 k-steps of HMMA.16816
        float acc[4][4];
#pragma unroll
        for (int n = 0; n < 4; n++)
#pragma unroll
            for (int j = 0; j < 4; j++) acc[n][j] = 0.f;

        const uint32_t bBase = smem_base + SM_B0 + (uint32_t)(cur * SM_BSZ);
        const uint32_t bAddr1 = bBase + (uint32_t)(brow * ASTRIDE + bkof);
        const uint32_t bAddr2 = bAddr1 + 16u * ASTRIDE;

#pragma unroll 4
        for (int ks = 0; ks < 32; ks++) {
            uint32_t af[4], bf1[4], bf2[4];
            ldsm_x4(af,  aAddr  + ks * 32);
            ldsm_x4(bf1, bAddr1 + ks * 32);
            ldsm_x4(bf2, bAddr2 + ks * 32);
            mma16816(acc[0], af, bf1[0], bf1[1]);
            mma16816(acc[1], af, bf1[2], bf1[3]);
            mma16816(acc[2], af, bf2[0], bf2[1]);
            mma16816(acc[3], af, bf2[2], bf2[3]);
        }

        // score + candidate tracking (approx scores, fp32 enorm)
        const int kt0 = t * TK;
#pragma unroll
        for (int n = 0; n < 4; n++) {
            const int kb = kt0 + n * 8 + tig * 2;
#pragma unroll
            for (int s2 = 0; s2 < 2; s2++) {
#pragma unroll
                for (int jj = 0; jj < 2; jj++) {
                    const int k = kb + jj;
                    float s = fmaf(-2.f, acc[n][s2 * 2 + jj], en_sm[k]);
                    if (s < bestv[s2] + EPS) {
                        int jm = 0; float vm = cv[s2][0];
#pragma unroll
                        for (int j = 1; j < 4; j++)
                            if (cv[s2][j] > vm) { vm = cv[s2][j]; jm = j; }
                        if (s < vm) { cv[s2][jm] = s; ci[s2][jm] = k; }
                        if (s < bestv[s2]) { bestv[s2] = s; besti[s2] = k; }
                    }
                }
            }
        }

        cp_wait0();
        __syncthreads();
    }

    // ---- finalize per row: quad merge + exact fp32 refinement ----
    const unsigned qmask = 0xFu << (lane & 28);
#pragma unroll
    for (int s2 = 0; s2 < 2; s2++) {
        const int m = wid * 16 + (lane >> 2) + s2 * 8;   // row in CTA (0..127)
        float bv = bestv[s2];
        int   bi = besti[s2];
#pragma unroll
        for (int off = 1; off <= 2; off <<= 1) {
            float ov = __shfl_xor_sync(qmask, bv, off);
            int   oi = __shfl_xor_sync(qmask, bi, off);
            if (ov < bv || (ov == bv && oi < bi)) { bv = ov; bi = oi; }
        }
        int cnt = 0;
#pragma unroll
        for (int j = 0; j < 4; j++)
            if (cv[s2][j] <= bv + EPS) cnt++;
        cnt += __shfl_xor_sync(qmask, cnt, 1);
        cnt += __shfl_xor_sync(qmask, cnt, 2);

        int choice = bi;
        if (cnt > 1) {
            float es = 3.402823e38f;
            int   ek = 0x7fffffff;
#pragma unroll
            for (int j = 0; j < 4; j++) {
                if (cv[s2][j] <= bv + EPS) {
                    const int kk2 = ci[s2][j];
                    const float* Er = E + (size_t)kk2 * D_;
                    float dot = 0.f;
#pragma unroll 8
                    for (int d = 0; d < D_; d++)
                        dot = fmaf(xb[(size_t)d * P_ + m], Er[d], dot);
                    float se = fmaf(-2.f, dot, en_sm[kk2]);
                    if (se < es || (se == es && kk2 < ek)) { es = se; ek = kk2; }
                }
            }
#pragma unroll
            for (int off = 1; off <= 2; off <<= 1) {
                float ov = __shfl_xor_sync(qmask, es, off);
                int   oi = __shfl_xor_sync(qmask, ek, off);
                if (ov < es || (ov == es && oi < ek)) { es = ov; ek = oi; }
            }
            choice = ek;
        }
        if ((lane & 3) == 0) kbest[m] = choice;
    }
    __syncthreads();

    // ---- gather + transpose write + loss (elementwise fp32 originals) ----
    const int p      = tid & 127;
    const int dstart = tid >> 7;
    const int myk    = kbest[p];
    const float* Er  = E + (size_t)myk * D_;
    float* ob        = out + (size_t)b * (D_ * P_) + p0;
    float lsum = 0.f;
#pragma unroll 4
    for (int d = dstart; d < D_; d += 2) {
        float q = Er[d];
        float z = xb[(size_t)d * P_ + p];
        ob[(size_t)d * P_ + p] = q;
        float df = z - q;
        lsum = fmaf(df, df, lsum);
    }

    __syncthreads();
    lred[tid] = lsum;
    __syncthreads();
    for (int s = 128; s > 0; s >>= 1) {
        if (tid < s) lred[tid] += lred[tid + s];
        __syncthreads();
    }
    if (tid == 0) g_losspart[blockIdx.x] = lred[0];
}

// ---------------------------------------------------------------------------
// Final loss: loss = 1.25 * mean((z-q)^2)
// ---------------------------------------------------------------------------
__global__ void loss_kernel(float* __restrict__ out, int write_loss) {
    __shared__ float sh[NBLK];
    int tid = threadIdx.x;
    sh[tid] = g_losspart[tid];
    __syncthreads();
    for (int s = NBLK / 2; s > 0; s >>= 1) {
        if (tid < s) sh[tid] += sh[tid + s];
        __syncthreads();
    }
    if (tid == 0 && write_loss) {
        float m = sh[0] / (float)((size_t)N_ * D_);
        out[(size_t)N_ * D_] = m + 0.25f * m;
    }
}

extern "C" void kernel_launch(void* const* d_in, const int* in_sizes, int n_in,
                              void* d_out, int out_size) {
    const float* x = (const float*)d_in[0];
    const float* E = (const float*)d_in[1];
    if (n_in >= 2 && in_sizes[0] == K_ * D_ && in_sizes[1] == N_ * D_) {
        const float* t = x; x = E; E = t;   // defensive input-order swap
    }
    float* out = (float*)d_out;

    cudaFuncSetAttribute(vq_main, cudaFuncAttributeMaxDynamicSharedMemorySize, SM_TOTAL);

    convE_kernel<<<K_ * D_ / 2 / 256, 256>>>(E);
    convZ_kernel<<<4096, 256>>>(x);
    enorm_kernel<<<K_ / 8, 256>>>(E);
    vq_main<<<NBLK, 256, SM_TOTAL>>>(x, E, out);
    loss_kernel<<<1, NBLK>>>(out, out_size > N_ * D_ ? 1 : 0);
}